// round 15
// baseline (speedup 1.0000x reference)
#include <cuda_runtime.h>
#include <cuda_fp16.h>
#include <cstdint>

#define N_NODES 100000
#define N_EDGES 640000
#define HDIM 128
#define H2DIM 256
#define EDIM 16

// ---------------- scratch (device globals) ------------------------------------
__device__ __half g_PQh [(size_t)N_NODES * 256];   // fp16: [0:128]=node@W1, [128:256]=node@W2
__device__ __half g_MSGh[(size_t)N_EDGES * HDIM];  // fp16 pre-BN messages
__device__ float  g_Y   [(size_t)N_NODES * HDIM];  // scatter target (fp32 accum)
__device__ float  g_H1  [(size_t)N_NODES * H2DIM]; // fp32 MLP intermediates
__device__ float  g_H2  [(size_t)N_NODES * H2DIM];
// BN stat slots: [0,128)=msg, [128,384)=bn1, [384,640)=bn2
__device__ float g_sum[640];
__device__ float g_sq [640];

// fp16 weights in [n][k] layout for HMMA (B operand = col-major)
#define OFF_NODE 0        // [256 n][128 k]  W1 | W2
#define OFF_M1   32768    // [256 n][128 k]
#define OFF_M2   65536    // [256 n][256 k]
#define OFF_M3   131072   // [128 n][256 k]
#define WH_TOTAL 163840
__device__ __half g_WallH[WH_TOTAL];
// edge weights fp16 [n][k]: k 0..127 = W3, 128..143 = We, stride 160
#define WEH_STRIDE 160
__device__ __half g_WedgeH[128 * WEH_STRIDE];

// ---------------- helpers ------------------------------------------------------
__device__ __forceinline__ void mma_f16(float* c, const unsigned* a, const unsigned* b) {
    asm volatile(
        "mma.sync.aligned.m16n8k16.row.col.f32.f16.f16.f32 "
        "{%0,%1,%2,%3}, {%4,%5,%6,%7}, {%8,%9}, {%0,%1,%2,%3};"
        : "+f"(c[0]), "+f"(c[1]), "+f"(c[2]), "+f"(c[3])
        : "r"(a[0]), "r"(a[1]), "r"(a[2]), "r"(a[3]), "r"(b[0]), "r"(b[1]));
}

__device__ __forceinline__ void cp16(uint32_t dst, const void* src, bool pred) {
    int sz = pred ? 16 : 0;
    asm volatile("cp.async.cg.shared.global [%0], [%1], 16, %2;"
                 :: "r"(dst), "l"(src), "r"(sz));
}
__device__ __forceinline__ void cp_commit() { asm volatile("cp.async.commit_group;"); }
template <int N> __device__ __forceinline__ void cp_wait() {
    asm volatile("cp.async.wait_group %0;" :: "n"(N));
}
__device__ __forceinline__ uint32_t s2u(const void* p) {
    uint32_t a;
    asm("{ .reg .u64 t; cvta.to.shared.u64 t, %1; cvt.u32.u64 %0, t; }" : "=r"(a) : "l"(p));
    return a;
}
__device__ __forceinline__ uint2 pack_half4(float4 v) {
    __half2 h0 = __floats2half2_rn(v.x, v.y);
    __half2 h1 = __floats2half2_rn(v.z, v.w);
    uint2 u;
    u.x = *(unsigned*)&h0;
    u.y = *(unsigned*)&h1;
    return u;
}
__device__ __forceinline__ float4 unpack_half4(unsigned ux, unsigned uy) {
    __half2 h0 = *(__half2*)&ux;
    __half2 h1 = *(__half2*)&uy;
    float2 f0 = __half22float2(h0);
    float2 f1 = __half22float2(h1);
    return make_float4(f0.x, f0.y, f1.x, f1.y);
}
__device__ __forceinline__ unsigned h2_from_f2(float2 f) {
    __half2 h = __float22half2_rn(f);
    return *(unsigned*)&h;
}

// dense GEMM smem: A 128x40 fp32, B 128x40 fp16, 3 stages (conflict-free)
#define G_ASTR 40
#define G_AS_STAGE (128 * G_ASTR * 4)   // 20480
#define G_BSH_STAGE (128 * 40 * 2)      // 10240
#define G_AS_BYTES (3 * G_AS_STAGE)     // 61440
#define G_BS_BYTES (3 * G_BSH_STAGE)    // 30720
#define G_PIPE (G_AS_BYTES + G_BS_BYTES)  // 92160
// edge smem: A 64x40 fp32, B 128x40 fp16, 2 stages
#define E_ASTR 40
#define E_AS_STAGE (64 * E_ASTR * 4)   // 10240
#define E_BSH_STAGE 10240              // 128*40*2
#define E_AS_BYTES (2 * E_AS_STAGE)    // 20480
#define E_PIPE (E_AS_BYTES + 2 * E_BSH_STAGE)  // 40960

// ---------------- prep: weight convert + zero Y/stats ---------------------------
#define PREP_TOTAL (WH_TOTAL + 128 * WEH_STRIDE)   // 184320
__global__ void prep_kernel(const float* __restrict__ W1, const float* __restrict__ W2,
                            const float* __restrict__ W3, const float* __restrict__ We,
                            const float* __restrict__ Wm1, const float* __restrict__ Wm2,
                            const float* __restrict__ Wm3) {
    size_t i = (size_t)blockIdx.x * blockDim.x + threadIdx.x;
    if (i < 32768) {
        int n = (int)i >> 7, k = (int)i & 127;
        float v = (n < 128) ? W1[k * 128 + n] : W2[k * 128 + (n - 128)];
        g_WallH[OFF_NODE + i] = __float2half_rn(v);
    } else if (i < 65536) {
        int j = (int)i - 32768;
        int n = j >> 7, k = j & 127;
        g_WallH[OFF_M1 + j] = __float2half_rn(Wm1[k * 256 + n]);
    } else if (i < 131072) {
        int j = (int)i - 65536;
        int n = j >> 8, k = j & 255;
        g_WallH[OFF_M2 + j] = __float2half_rn(Wm2[k * 256 + n]);
    } else if (i < WH_TOTAL) {
        int j = (int)i - 131072;
        int n = j >> 8, k = j & 255;
        g_WallH[OFF_M3 + j] = __float2half_rn(Wm3[k * 128 + n]);
    } else if (i < PREP_TOTAL) {
        int j = (int)i - WH_TOTAL;
        int n = j / WEH_STRIDE, k = j % WEH_STRIDE;
        float v = 0.f;
        if (k < 128)      v = W3[k * 128 + n];
        else if (k < 144) v = We[(k - 128) * 128 + n];
        g_WedgeH[j] = __float2half_rn(v);
    }
    const size_t tot = (size_t)N_NODES * HDIM;
    const size_t stride = (size_t)gridDim.x * blockDim.x;
    for (size_t p = i; p < tot; p += stride) g_Y[p] = 0.f;
    if (i < 640) { g_sum[i] = 0.f; g_sq[i] = 0.f; }
}

extern __shared__ char smem_raw[];

// ---------------- 3-stage pipelined fp16-HMMA GEMM with fused BN ----------------
// C[M,NC] = act(A) @ Wh^T (+cBias); Wh fp16 [n][k].
// BN-in computed in-kernel from raw stats. outHalf: fp16 C. sSum/sSq: stats out.
__global__ void __launch_bounds__(256, 2) gemm_mma_kernel(
    const float* __restrict__ A, const __half* __restrict__ Wh, int KSTR,
    void* __restrict__ Cout, int M, int K, int NC, int outHalf,
    const float* __restrict__ bnG, const float* __restrict__ bnB,
    const float* __restrict__ rawSum, const float* __restrict__ rawSq, float invCnt,
    const float* __restrict__ cBias,
    float* __restrict__ sSum, float* __restrict__ sSq)
{
    float  (*As)[128][G_ASTR] = reinterpret_cast<float(*)[128][G_ASTR]>(smem_raw);
    __half (*Bs)[128][40]     = reinterpret_cast<__half(*)[128][40]>(smem_raw + G_AS_BYTES);
    float  (*Cs)[132]         = reinterpret_cast<float(*)[132]>(smem_raw);   // overlay
    float* scs  = (float*)(smem_raw + G_PIPE);          // 256
    float* shs  = scs + 256;                            // 256
    float* red0 = shs + 256;                            // 128
    float* red1 = red0 + 128;                           // 128

    const int tid = threadIdx.x, lane = tid & 31, warp = tid >> 5;
    const int wm = (warp & 3) * 32, wn = (warp >> 2) * 64;
    const int g  = lane >> 2;
    const int c2 = (lane & 3) * 2;
    const int bm = blockIdx.y * 128, bn = blockIdx.x * 128;
    const bool useBN = (bnG != nullptr);

    const uint32_t AsAddr = s2u(smem_raw);
    const uint32_t BsAddr = AsAddr + G_AS_BYTES;

    if (useBN && tid < K) {
        float mean = rawSum[tid] * invCnt;
        float var  = fmaxf(rawSq[tid] * invCnt - mean * mean, 0.f);
        float a = bnG[tid] * rsqrtf(var + 1e-5f);
        scs[tid] = a;
        shs[tid] = fmaf(-mean, a, bnB[tid]);
    }

    auto issue_copy = [&](int t) {
        const int s = t % 3;
        const int k0 = t * 32;
#pragma unroll
        for (int l = 0; l < 4; l++) {
            int c = tid + l * 256;
            int row = c >> 3, cc = c & 7;
            int grow = bm + row;
            const float* src = A + (size_t)grow * K + k0 + cc * 4;
            uint32_t dst = AsAddr + (uint32_t)(s * G_AS_STAGE + (row * G_ASTR + cc * 4) * 4);
            cp16(dst, src, grow < M);
        }
#pragma unroll
        for (int l = 0; l < 2; l++) {
            int c = tid + l * 256;
            int row = c >> 2, cc = c & 3;
            const __half* src = Wh + (size_t)(bn + row) * KSTR + k0 + cc * 8;
            uint32_t dst = BsAddr + (uint32_t)(s * G_BSH_STAGE + (row * 40 + cc * 8) * 2);
            cp16(dst, src, true);
        }
        cp_commit();
    };

    float acc[2][8][4];
#pragma unroll
    for (int mt = 0; mt < 2; mt++)
#pragma unroll
        for (int nt = 0; nt < 8; nt++)
#pragma unroll
            for (int i = 0; i < 4; i++) acc[mt][nt][i] = 0.f;

    const int T = K >> 5;
    issue_copy(0);
    if (T > 1) issue_copy(1);

    for (int t = 0; t < T; t++) {
        if (t + 2 < T)      { issue_copy(t + 2); cp_wait<2>(); }
        else if (t + 1 < T) { cp_wait<1>(); }
        else                { cp_wait<0>(); }
        __syncthreads();
        const int s = t % 3;
        const int k0 = t * 32;
#pragma unroll
        for (int ks = 0; ks < 2; ks++) {
            const int kk = ks * 16;
            float2 scLo = make_float2(1.f, 1.f), shLo = make_float2(0.f, 0.f);
            float2 scHi = make_float2(1.f, 1.f), shHi = make_float2(0.f, 0.f);
            if (useBN) {
                scLo = *(const float2*)&scs[k0 + kk + c2];
                shLo = *(const float2*)&shs[k0 + kk + c2];
                scHi = *(const float2*)&scs[k0 + kk + c2 + 8];
                shHi = *(const float2*)&shs[k0 + kk + c2 + 8];
            }
            unsigned af[2][4], bf[8][2];
#pragma unroll
            for (int mt = 0; mt < 2; mt++) {
                int m = wm + mt * 16 + g;
                float2 a0 = *(const float2*)&As[s][m    ][kk + c2];
                float2 a1 = *(const float2*)&As[s][m + 8][kk + c2];
                float2 a2 = *(const float2*)&As[s][m    ][kk + c2 + 8];
                float2 a3 = *(const float2*)&As[s][m + 8][kk + c2 + 8];
                if (useBN) {
                    a0.x = fmaxf(fmaf(a0.x, scLo.x, shLo.x), 0.f);
                    a0.y = fmaxf(fmaf(a0.y, scLo.y, shLo.y), 0.f);
                    a1.x = fmaxf(fmaf(a1.x, scLo.x, shLo.x), 0.f);
                    a1.y = fmaxf(fmaf(a1.y, scLo.y, shLo.y), 0.f);
                    a2.x = fmaxf(fmaf(a2.x, scHi.x, shHi.x), 0.f);
                    a2.y = fmaxf(fmaf(a2.y, scHi.y, shHi.y), 0.f);
                    a3.x = fmaxf(fmaf(a3.x, scHi.x, shHi.x), 0.f);
                    a3.y = fmaxf(fmaf(a3.y, scHi.y, shHi.y), 0.f);
                }
                af[mt][0] = h2_from_f2(a0);
                af[mt][1] = h2_from_f2(a1);
                af[mt][2] = h2_from_f2(a2);
                af[mt][3] = h2_from_f2(a3);
            }
#pragma unroll
            for (int nt = 0; nt < 8; nt++) {
                int n = wn + nt * 8 + g;
                bf[nt][0] = *(const unsigned*)&Bs[s][n][kk + c2];
                bf[nt][1] = *(const unsigned*)&Bs[s][n][kk + c2 + 8];
            }
#pragma unroll
            for (int mt = 0; mt < 2; mt++)
#pragma unroll
                for (int nt = 0; nt < 8; nt++)
                    mma_f16(acc[mt][nt], af[mt], bf[nt]);
        }
        __syncthreads();
    }

    // ---------------- epilogue ----------------
#pragma unroll
    for (int mt = 0; mt < 2; mt++)
#pragma unroll
        for (int half = 0; half < 2; half++) {
            int r = wm + mt * 16 + g + half * 8;
#pragma unroll
            for (int nt = 0; nt < 8; nt++) {
                int cl = wn + nt * 8 + c2;
                float2 v; v.x = acc[mt][nt][half * 2 + 0]; v.y = acc[mt][nt][half * 2 + 1];
                *(float2*)&Cs[r][cl] = v;
            }
        }
    if (sSum && tid < 128) { red0[tid] = 0.f; red1[tid] = 0.f; }
    __syncthreads();

    float4 bias = make_float4(0.f, 0.f, 0.f, 0.f);
    if (cBias) bias = *(const float4*)(cBias + bn + lane * 4);
    float psum[4] = {0.f, 0.f, 0.f, 0.f}, psq[4] = {0.f, 0.f, 0.f, 0.f};

#pragma unroll
    for (int i = 0; i < 16; i++) {
        int r = warp * 16 + i;
        int R = bm + r;
        if (R < M) {
            float4 v = *(const float4*)&Cs[r][lane * 4];
            v.x += bias.x; v.y += bias.y; v.z += bias.z; v.w += bias.w;
            if (outHalf) {
                __half* Ch = (__half*)Cout;
                *(uint2*)(Ch + (size_t)R * NC + bn + lane * 4) = pack_half4(v);
            } else {
                float* Cf = (float*)Cout;
                *(float4*)(Cf + (size_t)R * NC + bn + lane * 4) = v;
            }
            psum[0] += v.x; psum[1] += v.y; psum[2] += v.z; psum[3] += v.w;
            psq[0] += v.x * v.x; psq[1] += v.y * v.y;
            psq[2] += v.z * v.z; psq[3] += v.w * v.w;
        }
    }

    if (sSum) {
        __syncthreads();
#pragma unroll
        for (int j = 0; j < 4; j++) {
            atomicAdd(&red0[lane * 4 + j], psum[j]);
            atomicAdd(&red1[lane * 4 + j], psq[j]);
        }
        __syncthreads();
        if (tid < 128) {
            atomicAdd(&sSum[bn + tid], red0[tid]);
            atomicAdd(&sSq [bn + tid], red1[tid]);
        }
    }
}

// ---------------- edge message kernel: fp16 HMMA, occ-4 -------------------------
__global__ void __launch_bounds__(256, 4) edge_msg_kernel(
    const float* __restrict__ edge_rep, const float* __restrict__ edge_attr,
    const int* __restrict__ src, const int* __restrict__ dst,
    const float* __restrict__ be)
{
    float  (*As)[64][E_ASTR] = reinterpret_cast<float(*)[64][E_ASTR]>(smem_raw);
    __half (*Bs)[128][40]    = reinterpret_cast<__half(*)[128][40]>(smem_raw + E_AS_BYTES);
    float  (*Cs)[132]        = reinterpret_cast<float(*)[132]>(smem_raw);   // overlay
    float* red0 = (float*)(smem_raw + E_PIPE);
    float* red1 = red0 + 128;

    const int tid = threadIdx.x, lane = tid & 31, warp = tid >> 5;
    const int wm = (warp & 1) * 32, wn = (warp >> 1) * 32;
    const int g  = lane >> 2;
    const int c2 = (lane & 3) * 2;
    const size_t bm = (size_t)blockIdx.x * 64;

    const uint32_t AsAddr = s2u(smem_raw);
    const uint32_t BsAddr = AsAddr + E_AS_BYTES;

    if (tid < 128) {
        int e0 = (int)bm + (tid >> 1);
        const __half* row = (tid & 1) ? (g_PQh + (size_t)dst[e0] * 256 + 128)
                                      : (g_PQh + (size_t)src[e0] * 256);
        asm volatile("prefetch.global.L2 [%0];" :: "l"(row));
        asm volatile("prefetch.global.L2 [%0];" :: "l"(row + 64));
    }

    auto issue_copy = [&](int t) {
        const int s = t & 1;
        if (t < 4) {
            const int k0 = t * 32;
#pragma unroll
            for (int l = 0; l < 2; l++) {
                int c = tid + l * 256;
                int row = c >> 3, cc = c & 7;
                const float* sp = edge_rep + (bm + row) * HDIM + k0 + cc * 4;
                uint32_t dp = AsAddr + (uint32_t)(s * E_AS_STAGE + (row * E_ASTR + cc * 4) * 4);
                cp16(dp, sp, true);
            }
#pragma unroll
            for (int l = 0; l < 2; l++) {
                int c = tid + l * 256;
                int row = c >> 2, cc = c & 3;
                const __half* sp = g_WedgeH + (size_t)row * WEH_STRIDE + k0 + cc * 8;
                uint32_t dp = BsAddr + (uint32_t)(s * E_BSH_STAGE + (row * 40 + cc * 8) * 2);
                cp16(dp, sp, true);
            }
        } else {
            {
                int row = tid >> 2, cc = tid & 3;
                const float* sp = edge_attr + (bm + row) * EDIM + cc * 4;
                uint32_t dp = AsAddr + (uint32_t)(s * E_AS_STAGE + (row * E_ASTR + cc * 4) * 4);
                cp16(dp, sp, true);
            }
            {
                int row = tid >> 1, cc = tid & 1;
                const __half* sp = g_WedgeH + (size_t)row * WEH_STRIDE + 128 + cc * 8;
                uint32_t dp = BsAddr + (uint32_t)(s * E_BSH_STAGE + (row * 40 + cc * 8) * 2);
                cp16(dp, sp, true);
            }
        }
        cp_commit();
    };

    float acc[2][4][4];
#pragma unroll
    for (int mt = 0; mt < 2; mt++)
#pragma unroll
        for (int nt = 0; nt < 4; nt++)
#pragma unroll
            for (int i = 0; i < 4; i++) acc[mt][nt][i] = 0.f;

    issue_copy(0);

#pragma unroll
    for (int t = 0; t < 5; t++) {
        cp_wait<0>();
        __syncthreads();
        if (t + 1 < 5) issue_copy(t + 1);
        const int s = t & 1;
        const int ksteps = (t < 4) ? 2 : 1;
#pragma unroll
        for (int ks = 0; ks < 2; ks++) {
            if (ks >= ksteps) break;
            const int kk = ks * 16;
            unsigned af[2][4], bf[4][2];
#pragma unroll
            for (int mt = 0; mt < 2; mt++) {
                int m = wm + mt * 16 + g;
                af[mt][0] = h2_from_f2(*(const float2*)&As[s][m    ][kk + c2]);
                af[mt][1] = h2_from_f2(*(const float2*)&As[s][m + 8][kk + c2]);
                af[mt][2] = h2_from_f2(*(const float2*)&As[s][m    ][kk + c2 + 8]);
                af[mt][3] = h2_from_f2(*(const float2*)&As[s][m + 8][kk + c2 + 8]);
            }
#pragma unroll
            for (int nt = 0; nt < 4; nt++) {
                int n = wn + nt * 8 + g;
                bf[nt][0] = *(const unsigned*)&Bs[s][n][kk + c2];
                bf[nt][1] = *(const unsigned*)&Bs[s][n][kk + c2 + 8];
            }
#pragma unroll
            for (int mt = 0; mt < 2; mt++)
#pragma unroll
                for (int nt = 0; nt < 4; nt++)
                    mma_f16(acc[mt][nt], af[mt], bf[nt]);
        }
        __syncthreads();
    }

#pragma unroll
    for (int mt = 0; mt < 2; mt++)
#pragma unroll
        for (int half = 0; half < 2; half++) {
            int r = wm + mt * 16 + g + half * 8;
#pragma unroll
            for (int nt = 0; nt < 4; nt++) {
                int cl = wn + nt * 8 + c2;
                float2 v; v.x = acc[mt][nt][half * 2 + 0]; v.y = acc[mt][nt][half * 2 + 1];
                *(float2*)&Cs[r][cl] = v;
            }
        }
    if (tid < 128) { red0[tid] = 0.f; red1[tid] = 0.f; }
    __syncthreads();

    float4 bev = *(const float4*)(be + lane * 4);
    float psum[4] = {0.f, 0.f, 0.f, 0.f}, psq[4] = {0.f, 0.f, 0.f, 0.f};

#pragma unroll
    for (int i = 0; i < 8; i++) {
        int r = warp * 8 + i;
        size_t e = bm + r;
        int s = src[e], d = dst[e];
        uint2 pu = *(const uint2*)(g_PQh + (size_t)s * 256 + lane * 4);
        uint2 qu = *(const uint2*)(g_PQh + (size_t)d * 256 + 128 + lane * 4);
        float4 pv = unpack_half4(pu.x, pu.y);
        float4 qv = unpack_half4(qu.x, qu.y);
        float4 v = *(const float4*)&Cs[r][lane * 4];
        v.x += pv.x + qv.x + bev.x;
        v.y += pv.y + qv.y + bev.y;
        v.z += pv.z + qv.z + bev.z;
        v.w += pv.w + qv.w + bev.w;
        *(uint2*)(g_MSGh + e * HDIM + lane * 4) = pack_half4(v);
        psum[0] += v.x; psum[1] += v.y; psum[2] += v.z; psum[3] += v.w;
        psq[0] += v.x * v.x; psq[1] += v.y * v.y;
        psq[2] += v.z * v.z; psq[3] += v.w * v.w;
    }

    __syncthreads();
#pragma unroll
    for (int j = 0; j < 4; j++) {
        atomicAdd(&red0[lane * 4 + j], psum[j]);
        atomicAdd(&red1[lane * 4 + j], psq[j]);
    }
    __syncthreads();
    if (tid < 128) {
        atomicAdd(&g_sum[tid], red0[tid]);
        atomicAdd(&g_sq [tid], red1[tid]);
    }
}

// ---------------- scatter: fused msg-BN finalize + 8 cols/thread ----------------
__global__ void __launch_bounds__(256) scatter_kernel(const int* __restrict__ dst,
                                                      const float* __restrict__ bng,
                                                      const float* __restrict__ bnb) {
    __shared__ float ssc[128], ssh[128];
    const int tid = threadIdx.x;
    if (tid < 128) {
        const float invE = 1.f / (float)N_EDGES;
        float mean = g_sum[tid] * invE;
        float var  = fmaxf(g_sq[tid] * invE - mean * mean, 0.f);
        float a = bng[tid] * rsqrtf(var + 1e-5f);
        ssc[tid] = a;
        ssh[tid] = fmaf(-mean, a, bnb[tid]);
    }
    __syncthreads();

    unsigned t = blockIdx.x * blockDim.x + tid;
    size_t e = (size_t)(t >> 4);       // 16 threads per edge
    int c8 = (t & 15) * 8;
    if (e < (size_t)N_EDGES) {
        int d = dst[e];
        uint4 m4 = *(const uint4*)(g_MSGh + e * HDIM + c8);
        float4 m0 = unpack_half4(m4.x, m4.y);
        float4 m1 = unpack_half4(m4.z, m4.w);
        float4 s0 = *(const float4*)&ssc[c8];
        float4 s1 = *(const float4*)&ssc[c8 + 4];
        float4 h0 = *(const float4*)&ssh[c8];
        float4 h1 = *(const float4*)&ssh[c8 + 4];
        float v0 = fmaxf(fmaf(m0.x, s0.x, h0.x), 0.f);
        float v1 = fmaxf(fmaf(m0.y, s0.y, h0.y), 0.f);
        float v2 = fmaxf(fmaf(m0.z, s0.z, h0.z), 0.f);
        float v3 = fmaxf(fmaf(m0.w, s0.w, h0.w), 0.f);
        float v4 = fmaxf(fmaf(m1.x, s1.x, h1.x), 0.f);
        float v5 = fmaxf(fmaf(m1.y, s1.y, h1.y), 0.f);
        float v6 = fmaxf(fmaf(m1.z, s1.z, h1.z), 0.f);
        float v7 = fmaxf(fmaf(m1.w, s1.w, h1.w), 0.f);
        float* p = g_Y + (size_t)d * HDIM + c8;
        asm volatile("red.global.add.v4.f32 [%0], {%1,%2,%3,%4};"
                     :: "l"(p), "f"(v0), "f"(v1), "f"(v2), "f"(v3) : "memory");
        asm volatile("red.global.add.v4.f32 [%0], {%1,%2,%3,%4};"
                     :: "l"(p + 4), "f"(v4), "f"(v5), "f"(v6), "f"(v7) : "memory");
    }
}

// ---------------- launch ------------------------------------------------------
extern "C" void kernel_launch(void* const* d_in, const int* in_sizes, int n_in,
                              void* d_out, int out_size) {
    const float* node_rep  = (const float*)d_in[0];
    const float* edge_rep  = (const float*)d_in[1];
    const float* edge_attr = (const float*)d_in[2];
    const int*   eidx      = (const int*)d_in[3];
    const float* W1  = (const float*)d_in[4];
    const float* W2  = (const float*)d_in[5];
    const float* W3  = (const float*)d_in[6];
    const float* We  = (const float*)d_in[7];
    const float* be  = (const float*)d_in[8];
    const float* bng = (const float*)d_in[9];
    const float* bnb = (const float*)d_in[10];
    const float* Wm1 = (const float*)d_in[11];
    const float* g1  = (const float*)d_in[12];
    const float* b1  = (const float*)d_in[13];
    const float* Wm2 = (const float*)d_in[14];
    const float* g2  = (const float*)d_in[15];
    const float* b2  = (const float*)d_in[16];
    const float* Wm3 = (const float*)d_in[17];
    const float* bm3 = (const float*)d_in[18];
    float* out = (float*)d_out;

    const int* src = eidx;
    const int* dst = eidx + N_EDGES;

    float *Y, *H1, *H2, *SUM, *SQ;
    __half *PQh, *WH;
    cudaGetSymbolAddress((void**)&PQh, g_PQh);
    cudaGetSymbolAddress((void**)&Y,  g_Y);
    cudaGetSymbolAddress((void**)&H1, g_H1);
    cudaGetSymbolAddress((void**)&H2, g_H2);
    cudaGetSymbolAddress((void**)&SUM, g_sum);
    cudaGetSymbolAddress((void**)&SQ,  g_sq);
    cudaGetSymbolAddress((void**)&WH,  g_WallH);

    const int GEMM_SMEM = G_PIPE + 2048 + 1024;   // 95232
    const int EDGE_SMEM = E_PIPE + 1024;          // 41984
    cudaFuncSetAttribute(gemm_mma_kernel, cudaFuncAttributeMaxDynamicSharedMemorySize, GEMM_SMEM);
    cudaFuncSetAttribute(edge_msg_kernel, cudaFuncAttributeMaxDynamicSharedMemorySize, EDGE_SMEM);

    const int MBLK = (N_NODES + 127) / 128;  // 782
    const float invN = 1.f / (float)N_NODES;

    prep_kernel<<<4096, 256>>>(W1, W2, W3, We, Wm1, Wm2, Wm3);

    // fused node linears: PQ = node_rep @ [W1|W2] -> fp16
    gemm_mma_kernel<<<dim3(2, MBLK), 256, GEMM_SMEM>>>(
        node_rep, WH + OFF_NODE, HDIM, PQh, N_NODES, HDIM, 256, 1,
        nullptr, nullptr, nullptr, nullptr, 0.f, nullptr, nullptr, nullptr);

    // edge GEMM (fp16 HMMA, occ-4) + encoder + gathers + BN stats
    edge_msg_kernel<<<N_EDGES / 64, 256, EDGE_SMEM>>>(edge_rep, edge_attr, src, dst, be);

    // BN finalize (in-block) + BN + ReLU + scatter-sum
    scatter_kernel<<<(N_EDGES * 16) / 256, 256>>>(dst, bng, bnb);

    // MLP layer 1: H1 = Y @ Wm1, stats -> slot 128
    gemm_mma_kernel<<<dim3(2, MBLK), 256, GEMM_SMEM>>>(
        Y, WH + OFF_M1, HDIM, H1, N_NODES, HDIM, H2DIM, 0,
        nullptr, nullptr, nullptr, nullptr, 0.f, nullptr, SUM + 128, SQ + 128);

    // MLP layer 2: H2 = relu(bn1(H1)) @ Wm2 (bn1 finalize fused in-kernel)
    gemm_mma_kernel<<<dim3(2, MBLK), 256, GEMM_SMEM>>>(
        H1, WH + OFF_M2, H2DIM, H2, N_NODES, H2DIM, H2DIM, 0,
        g1, b1, SUM + 128, SQ + 128, invN, nullptr, SUM + 384, SQ + 384);

    // MLP layer 3: out = relu(bn2(H2)) @ Wm3 + bm3 (bn2 finalize fused in-kernel)
    gemm_mma_kernel<<<dim3(1, MBLK), 256, GEMM_SMEM>>>(
        H2, WH + OFF_M3, H2DIM, out, N_NODES, H2DIM, HDIM, 0,
        g2, b2, SUM + 384, SQ + 384, invN, bm3, nullptr, nullptr);
}

// round 16
// speedup vs baseline: 1.0013x; 1.0013x over previous
#include <cuda_runtime.h>
#include <cuda_fp16.h>
#include <cstdint>

#define N_NODES 100000
#define N_EDGES 640000
#define HDIM 128
#define H2DIM 256
#define EDIM 16

// ---------------- scratch (device globals) ------------------------------------
__device__ __half g_PQh [(size_t)N_NODES * 256];   // fp16: [0:128]=node@W1, [128:256]=node@W2
__device__ __half g_MSGh[(size_t)N_EDGES * HDIM];  // fp16 pre-BN messages
__device__ float  g_Y   [(size_t)N_NODES * HDIM];  // scatter target (fp32 accum)
__device__ float  g_H1  [(size_t)N_NODES * H2DIM]; // fp32 MLP intermediates
__device__ float  g_H2  [(size_t)N_NODES * H2DIM];
// BN stat slots: [0,128)=msg, [128,384)=bn1, [384,640)=bn2
__device__ float g_sum[640];
__device__ float g_sq [640];

// fp16 weights in [n][k] layout for HMMA (B operand = col-major)
#define OFF_NODE 0        // [256 n][128 k]  W1 | W2
#define OFF_M1   32768    // [256 n][128 k]
#define OFF_M2   65536    // [256 n][256 k]
#define OFF_M3   131072   // [128 n][256 k]
#define WH_TOTAL 163840
__device__ __half g_WallH[WH_TOTAL];
// edge weights fp16 [n][k]: k 0..127 = W3, 128..143 = We, stride 160
#define WEH_STRIDE 160
__device__ __half g_WedgeH[128 * WEH_STRIDE];

// ---------------- helpers ------------------------------------------------------
__device__ __forceinline__ void mma_f16(float* c, const unsigned* a, const unsigned* b) {
    asm volatile(
        "mma.sync.aligned.m16n8k16.row.col.f32.f16.f16.f32 "
        "{%0,%1,%2,%3}, {%4,%5,%6,%7}, {%8,%9}, {%0,%1,%2,%3};"
        : "+f"(c[0]), "+f"(c[1]), "+f"(c[2]), "+f"(c[3])
        : "r"(a[0]), "r"(a[1]), "r"(a[2]), "r"(a[3]), "r"(b[0]), "r"(b[1]));
}

__device__ __forceinline__ void cp16(uint32_t dst, const void* src, bool pred) {
    int sz = pred ? 16 : 0;
    asm volatile("cp.async.cg.shared.global [%0], [%1], 16, %2;"
                 :: "r"(dst), "l"(src), "r"(sz));
}
__device__ __forceinline__ void cp_commit() { asm volatile("cp.async.commit_group;"); }
template <int N> __device__ __forceinline__ void cp_wait() {
    asm volatile("cp.async.wait_group %0;" :: "n"(N));
}
__device__ __forceinline__ uint32_t s2u(const void* p) {
    uint32_t a;
    asm("{ .reg .u64 t; cvta.to.shared.u64 t, %1; cvt.u32.u64 %0, t; }" : "=r"(a) : "l"(p));
    return a;
}
__device__ __forceinline__ uint2 pack_half4(float4 v) {
    __half2 h0 = __floats2half2_rn(v.x, v.y);
    __half2 h1 = __floats2half2_rn(v.z, v.w);
    uint2 u;
    u.x = *(unsigned*)&h0;
    u.y = *(unsigned*)&h1;
    return u;
}
__device__ __forceinline__ float4 unpack_half4(unsigned ux, unsigned uy) {
    __half2 h0 = *(__half2*)&ux;
    __half2 h1 = *(__half2*)&uy;
    float2 f0 = __half22float2(h0);
    float2 f1 = __half22float2(h1);
    return make_float4(f0.x, f0.y, f1.x, f1.y);
}
__device__ __forceinline__ unsigned h2_from_f2(float2 f) {
    __half2 h = __float22half2_rn(f);
    return *(unsigned*)&h;
}

// dense GEMM smem: A 128x40 fp32, B 128x40 fp16, 3 stages (conflict-free)
#define G_ASTR 40
#define G_AS_STAGE (128 * G_ASTR * 4)   // 20480
#define G_BSH_STAGE (128 * 40 * 2)      // 10240
#define G_AS_BYTES (3 * G_AS_STAGE)     // 61440
#define G_BS_BYTES (3 * G_BSH_STAGE)    // 30720
#define G_PIPE (G_AS_BYTES + G_BS_BYTES)  // 92160
// edge smem: A 64x40 fp32, B 128x40 fp16, 2 stages
#define E_ASTR 40
#define E_AS_STAGE (64 * E_ASTR * 4)   // 10240
#define E_BSH_STAGE 10240              // 128*40*2
#define E_AS_BYTES (2 * E_AS_STAGE)    // 20480
#define E_PIPE (E_AS_BYTES + 2 * E_BSH_STAGE)  // 40960

// ---------------- prep: weight convert + zero Y/stats ---------------------------
#define PREP_TOTAL (WH_TOTAL + 128 * WEH_STRIDE)   // 184320
__global__ void prep_kernel(const float* __restrict__ W1, const float* __restrict__ W2,
                            const float* __restrict__ W3, const float* __restrict__ We,
                            const float* __restrict__ Wm1, const float* __restrict__ Wm2,
                            const float* __restrict__ Wm3) {
    size_t i = (size_t)blockIdx.x * blockDim.x + threadIdx.x;
    if (i < 32768) {
        int n = (int)i >> 7, k = (int)i & 127;
        float v = (n < 128) ? W1[k * 128 + n] : W2[k * 128 + (n - 128)];
        g_WallH[OFF_NODE + i] = __float2half_rn(v);
    } else if (i < 65536) {
        int j = (int)i - 32768;
        int n = j >> 7, k = j & 127;
        g_WallH[OFF_M1 + j] = __float2half_rn(Wm1[k * 256 + n]);
    } else if (i < 131072) {
        int j = (int)i - 65536;
        int n = j >> 8, k = j & 255;
        g_WallH[OFF_M2 + j] = __float2half_rn(Wm2[k * 256 + n]);
    } else if (i < WH_TOTAL) {
        int j = (int)i - 131072;
        int n = j >> 8, k = j & 255;
        g_WallH[OFF_M3 + j] = __float2half_rn(Wm3[k * 128 + n]);
    } else if (i < PREP_TOTAL) {
        int j = (int)i - WH_TOTAL;
        int n = j / WEH_STRIDE, k = j % WEH_STRIDE;
        float v = 0.f;
        if (k < 128)      v = W3[k * 128 + n];
        else if (k < 144) v = We[(k - 128) * 128 + n];
        g_WedgeH[j] = __float2half_rn(v);
    }
    const size_t tot = (size_t)N_NODES * HDIM;
    const size_t stride = (size_t)gridDim.x * blockDim.x;
    for (size_t p = i; p < tot; p += stride) g_Y[p] = 0.f;
    if (i < 640) { g_sum[i] = 0.f; g_sq[i] = 0.f; }
}

extern __shared__ char smem_raw[];

// ---------------- 3-stage pipelined fp16-HMMA GEMM, 1 sync/tile -----------------
// C[M,NC] = act(A) @ Wh^T (+cBias); Wh fp16 [n][k].
// BN-in computed in-kernel from raw stats. outHalf: fp16 C. sSum/sSq: stats out.
__global__ void __launch_bounds__(256, 2) gemm_mma_kernel(
    const float* __restrict__ A, const __half* __restrict__ Wh, int KSTR,
    void* __restrict__ Cout, int M, int K, int NC, int outHalf,
    const float* __restrict__ bnG, const float* __restrict__ bnB,
    const float* __restrict__ rawSum, const float* __restrict__ rawSq, float invCnt,
    const float* __restrict__ cBias,
    float* __restrict__ sSum, float* __restrict__ sSq)
{
    float  (*As)[128][G_ASTR] = reinterpret_cast<float(*)[128][G_ASTR]>(smem_raw);
    __half (*Bs)[128][40]     = reinterpret_cast<__half(*)[128][40]>(smem_raw + G_AS_BYTES);
    float  (*Cs)[132]         = reinterpret_cast<float(*)[132]>(smem_raw);   // overlay
    float* scs  = (float*)(smem_raw + G_PIPE);          // 256
    float* shs  = scs + 256;                            // 256
    float* red0 = shs + 256;                            // 128
    float* red1 = red0 + 128;                           // 128

    const int tid = threadIdx.x, lane = tid & 31, warp = tid >> 5;
    const int wm = (warp & 3) * 32, wn = (warp >> 2) * 64;
    const int g  = lane >> 2;
    const int c2 = (lane & 3) * 2;
    const int bm = blockIdx.y * 128, bn = blockIdx.x * 128;
    const bool useBN = (bnG != nullptr);

    const uint32_t AsAddr = s2u(smem_raw);
    const uint32_t BsAddr = AsAddr + G_AS_BYTES;

    if (useBN && tid < K) {
        float mean = rawSum[tid] * invCnt;
        float var  = fmaxf(rawSq[tid] * invCnt - mean * mean, 0.f);
        float a = bnG[tid] * rsqrtf(var + 1e-5f);
        scs[tid] = a;
        shs[tid] = fmaf(-mean, a, bnB[tid]);
    }

    auto issue_copy = [&](int t) {
        const int s = t % 3;
        const int k0 = t * 32;
#pragma unroll
        for (int l = 0; l < 4; l++) {
            int c = tid + l * 256;
            int row = c >> 3, cc = c & 7;
            int grow = bm + row;
            const float* src = A + (size_t)grow * K + k0 + cc * 4;
            uint32_t dst = AsAddr + (uint32_t)(s * G_AS_STAGE + (row * G_ASTR + cc * 4) * 4);
            cp16(dst, src, grow < M);
        }
#pragma unroll
        for (int l = 0; l < 2; l++) {
            int c = tid + l * 256;
            int row = c >> 2, cc = c & 3;
            const __half* src = Wh + (size_t)(bn + row) * KSTR + k0 + cc * 8;
            uint32_t dst = BsAddr + (uint32_t)(s * G_BSH_STAGE + (row * 40 + cc * 8) * 2);
            cp16(dst, src, true);
        }
        cp_commit();
    };

    float acc[2][8][4];
#pragma unroll
    for (int mt = 0; mt < 2; mt++)
#pragma unroll
        for (int nt = 0; nt < 8; nt++)
#pragma unroll
            for (int i = 0; i < 4; i++) acc[mt][nt][i] = 0.f;

    const int T = K >> 5;
    issue_copy(0);
    if (T > 1) issue_copy(1);

    // single sync per tile: wait -> sync -> issue(t+2) -> compute(t).
    // The leading sync at iter t guarantees all warps finished compute(t-1),
    // which is the stage issue(t+2) overwrites ((t+2)%3 == (t-1)%3).
    for (int t = 0; t < T; t++) {
        if (t + 1 < T) { cp_wait<1>(); }
        else           { cp_wait<0>(); }
        __syncthreads();
        if (t + 2 < T) issue_copy(t + 2);
        const int s = t % 3;
        const int k0 = t * 32;
#pragma unroll
        for (int ks = 0; ks < 2; ks++) {
            const int kk = ks * 16;
            float2 scLo = make_float2(1.f, 1.f), shLo = make_float2(0.f, 0.f);
            float2 scHi = make_float2(1.f, 1.f), shHi = make_float2(0.f, 0.f);
            if (useBN) {
                scLo = *(const float2*)&scs[k0 + kk + c2];
                shLo = *(const float2*)&shs[k0 + kk + c2];
                scHi = *(const float2*)&scs[k0 + kk + c2 + 8];
                shHi = *(const float2*)&shs[k0 + kk + c2 + 8];
            }
            unsigned af[2][4], bf[8][2];
#pragma unroll
            for (int mt = 0; mt < 2; mt++) {
                int m = wm + mt * 16 + g;
                float2 a0 = *(const float2*)&As[s][m    ][kk + c2];
                float2 a1 = *(const float2*)&As[s][m + 8][kk + c2];
                float2 a2 = *(const float2*)&As[s][m    ][kk + c2 + 8];
                float2 a3 = *(const float2*)&As[s][m + 8][kk + c2 + 8];
                if (useBN) {
                    a0.x = fmaxf(fmaf(a0.x, scLo.x, shLo.x), 0.f);
                    a0.y = fmaxf(fmaf(a0.y, scLo.y, shLo.y), 0.f);
                    a1.x = fmaxf(fmaf(a1.x, scLo.x, shLo.x), 0.f);
                    a1.y = fmaxf(fmaf(a1.y, scLo.y, shLo.y), 0.f);
                    a2.x = fmaxf(fmaf(a2.x, scHi.x, shHi.x), 0.f);
                    a2.y = fmaxf(fmaf(a2.y, scHi.y, shHi.y), 0.f);
                    a3.x = fmaxf(fmaf(a3.x, scHi.x, shHi.x), 0.f);
                    a3.y = fmaxf(fmaf(a3.y, scHi.y, shHi.y), 0.f);
                }
                af[mt][0] = h2_from_f2(a0);
                af[mt][1] = h2_from_f2(a1);
                af[mt][2] = h2_from_f2(a2);
                af[mt][3] = h2_from_f2(a3);
            }
#pragma unroll
            for (int nt = 0; nt < 8; nt++) {
                int n = wn + nt * 8 + g;
                bf[nt][0] = *(const unsigned*)&Bs[s][n][kk + c2];
                bf[nt][1] = *(const unsigned*)&Bs[s][n][kk + c2 + 8];
            }
#pragma unroll
            for (int mt = 0; mt < 2; mt++)
#pragma unroll
                for (int nt = 0; nt < 8; nt++)
                    mma_f16(acc[mt][nt], af[mt], bf[nt]);
        }
    }

    // protect smem overlay: all warps must finish last compute before Cs writes
    __syncthreads();

    // ---------------- epilogue ----------------
#pragma unroll
    for (int mt = 0; mt < 2; mt++)
#pragma unroll
        for (int half = 0; half < 2; half++) {
            int r = wm + mt * 16 + g + half * 8;
#pragma unroll
            for (int nt = 0; nt < 8; nt++) {
                int cl = wn + nt * 8 + c2;
                float2 v; v.x = acc[mt][nt][half * 2 + 0]; v.y = acc[mt][nt][half * 2 + 1];
                *(float2*)&Cs[r][cl] = v;
            }
        }
    if (sSum && tid < 128) { red0[tid] = 0.f; red1[tid] = 0.f; }
    __syncthreads();

    float4 bias = make_float4(0.f, 0.f, 0.f, 0.f);
    if (cBias) bias = *(const float4*)(cBias + bn + lane * 4);
    float psum[4] = {0.f, 0.f, 0.f, 0.f}, psq[4] = {0.f, 0.f, 0.f, 0.f};

#pragma unroll
    for (int i = 0; i < 16; i++) {
        int r = warp * 16 + i;
        int R = bm + r;
        if (R < M) {
            float4 v = *(const float4*)&Cs[r][lane * 4];
            v.x += bias.x; v.y += bias.y; v.z += bias.z; v.w += bias.w;
            if (outHalf) {
                __half* Ch = (__half*)Cout;
                *(uint2*)(Ch + (size_t)R * NC + bn + lane * 4) = pack_half4(v);
            } else {
                float* Cf = (float*)Cout;
                *(float4*)(Cf + (size_t)R * NC + bn + lane * 4) = v;
            }
            psum[0] += v.x; psum[1] += v.y; psum[2] += v.z; psum[3] += v.w;
            psq[0] += v.x * v.x; psq[1] += v.y * v.y;
            psq[2] += v.z * v.z; psq[3] += v.w * v.w;
        }
    }

    if (sSum) {
        __syncthreads();
#pragma unroll
        for (int j = 0; j < 4; j++) {
            atomicAdd(&red0[lane * 4 + j], psum[j]);
            atomicAdd(&red1[lane * 4 + j], psq[j]);
        }
        __syncthreads();
        if (tid < 128) {
            atomicAdd(&sSum[bn + tid], red0[tid]);
            atomicAdd(&sSq [bn + tid], red1[tid]);
        }
    }
}

// ---------------- edge message kernel: fp16 HMMA, occ-4, 1 sync/tile ------------
__global__ void __launch_bounds__(256, 4) edge_msg_kernel(
    const float* __restrict__ edge_rep, const float* __restrict__ edge_attr,
    const int* __restrict__ src, const int* __restrict__ dst,
    const float* __restrict__ be)
{
    float  (*As)[64][E_ASTR] = reinterpret_cast<float(*)[64][E_ASTR]>(smem_raw);
    __half (*Bs)[128][40]    = reinterpret_cast<__half(*)[128][40]>(smem_raw + E_AS_BYTES);
    float  (*Cs)[132]        = reinterpret_cast<float(*)[132]>(smem_raw);   // overlay
    float* red0 = (float*)(smem_raw + E_PIPE);
    float* red1 = red0 + 128;

    const int tid = threadIdx.x, lane = tid & 31, warp = tid >> 5;
    const int wm = (warp & 1) * 32, wn = (warp >> 1) * 32;
    const int g  = lane >> 2;
    const int c2 = (lane & 3) * 2;
    const size_t bm = (size_t)blockIdx.x * 64;

    const uint32_t AsAddr = s2u(smem_raw);
    const uint32_t BsAddr = AsAddr + E_AS_BYTES;

    if (tid < 128) {
        int e0 = (int)bm + (tid >> 1);
        const __half* row = (tid & 1) ? (g_PQh + (size_t)dst[e0] * 256 + 128)
                                      : (g_PQh + (size_t)src[e0] * 256);
        asm volatile("prefetch.global.L2 [%0];" :: "l"(row));
        asm volatile("prefetch.global.L2 [%0];" :: "l"(row + 64));
    }

    auto issue_copy = [&](int t) {
        const int s = t & 1;
        if (t < 4) {
            const int k0 = t * 32;
#pragma unroll
            for (int l = 0; l < 2; l++) {
                int c = tid + l * 256;
                int row = c >> 3, cc = c & 7;
                const float* sp = edge_rep + (bm + row) * HDIM + k0 + cc * 4;
                uint32_t dp = AsAddr + (uint32_t)(s * E_AS_STAGE + (row * E_ASTR + cc * 4) * 4);
                cp16(dp, sp, true);
            }
#pragma unroll
            for (int l = 0; l < 2; l++) {
                int c = tid + l * 256;
                int row = c >> 2, cc = c & 3;
                const __half* sp = g_WedgeH + (size_t)row * WEH_STRIDE + k0 + cc * 8;
                uint32_t dp = BsAddr + (uint32_t)(s * E_BSH_STAGE + (row * 40 + cc * 8) * 2);
                cp16(dp, sp, true);
            }
        } else {
            {
                int row = tid >> 2, cc = tid & 3;
                const float* sp = edge_attr + (bm + row) * EDIM + cc * 4;
                uint32_t dp = AsAddr + (uint32_t)(s * E_AS_STAGE + (row * E_ASTR + cc * 4) * 4);
                cp16(dp, sp, true);
            }
            {
                int row = tid >> 1, cc = tid & 1;
                const __half* sp = g_WedgeH + (size_t)row * WEH_STRIDE + 128 + cc * 8;
                uint32_t dp = BsAddr + (uint32_t)(s * E_BSH_STAGE + (row * 40 + cc * 8) * 2);
                cp16(dp, sp, true);
            }
        }
        cp_commit();
    };

    float acc[2][4][4];
#pragma unroll
    for (int mt = 0; mt < 2; mt++)
#pragma unroll
        for (int nt = 0; nt < 4; nt++)
#pragma unroll
            for (int i = 0; i < 4; i++) acc[mt][nt][i] = 0.f;

    issue_copy(0);

    // single sync per tile (leading sync protects issue(t+1)'s stage reuse)
#pragma unroll
    for (int t = 0; t < 5; t++) {
        cp_wait<0>();
        __syncthreads();
        if (t + 1 < 5) issue_copy(t + 1);
        const int s = t & 1;
        const int ksteps = (t < 4) ? 2 : 1;
#pragma unroll
        for (int ks = 0; ks < 2; ks++) {
            if (ks >= ksteps) break;
            const int kk = ks * 16;
            unsigned af[2][4], bf[4][2];
#pragma unroll
            for (int mt = 0; mt < 2; mt++) {
                int m = wm + mt * 16 + g;
                af[mt][0] = h2_from_f2(*(const float2*)&As[s][m    ][kk + c2]);
                af[mt][1] = h2_from_f2(*(const float2*)&As[s][m + 8][kk + c2]);
                af[mt][2] = h2_from_f2(*(const float2*)&As[s][m    ][kk + c2 + 8]);
                af[mt][3] = h2_from_f2(*(const float2*)&As[s][m + 8][kk + c2 + 8]);
            }
#pragma unroll
            for (int nt = 0; nt < 4; nt++) {
                int n = wn + nt * 8 + g;
                bf[nt][0] = *(const unsigned*)&Bs[s][n][kk + c2];
                bf[nt][1] = *(const unsigned*)&Bs[s][n][kk + c2 + 8];
            }
#pragma unroll
            for (int mt = 0; mt < 2; mt++)
#pragma unroll
                for (int nt = 0; nt < 4; nt++)
                    mma_f16(acc[mt][nt], af[mt], bf[nt]);
        }
    }

    // protect smem overlay
    __syncthreads();

#pragma unroll
    for (int mt = 0; mt < 2; mt++)
#pragma unroll
        for (int half = 0; half < 2; half++) {
            int r = wm + mt * 16 + g + half * 8;
#pragma unroll
            for (int nt = 0; nt < 4; nt++) {
                int cl = wn + nt * 8 + c2;
                float2 v; v.x = acc[mt][nt][half * 2 + 0]; v.y = acc[mt][nt][half * 2 + 1];
                *(float2*)&Cs[r][cl] = v;
            }
        }
    if (tid < 128) { red0[tid] = 0.f; red1[tid] = 0.f; }
    __syncthreads();

    float4 bev = *(const float4*)(be + lane * 4);
    float psum[4] = {0.f, 0.f, 0.f, 0.f}, psq[4] = {0.f, 0.f, 0.f, 0.f};

#pragma unroll
    for (int i = 0; i < 8; i++) {
        int r = warp * 8 + i;
        size_t e = bm + r;
        int s = src[e], d = dst[e];
        uint2 pu = *(const uint2*)(g_PQh + (size_t)s * 256 + lane * 4);
        uint2 qu = *(const uint2*)(g_PQh + (size_t)d * 256 + 128 + lane * 4);
        float4 pv = unpack_half4(pu.x, pu.y);
        float4 qv = unpack_half4(qu.x, qu.y);
        float4 v = *(const float4*)&Cs[r][lane * 4];
        v.x += pv.x + qv.x + bev.x;
        v.y += pv.y + qv.y + bev.y;
        v.z += pv.z + qv.z + bev.z;
        v.w += pv.w + qv.w + bev.w;
        *(uint2*)(g_MSGh + e * HDIM + lane * 4) = pack_half4(v);
        psum[0] += v.x; psum[1] += v.y; psum[2] += v.z; psum[3] += v.w;
        psq[0] += v.x * v.x; psq[1] += v.y * v.y;
        psq[2] += v.z * v.z; psq[3] += v.w * v.w;
    }

    __syncthreads();
#pragma unroll
    for (int j = 0; j < 4; j++) {
        atomicAdd(&red0[lane * 4 + j], psum[j]);
        atomicAdd(&red1[lane * 4 + j], psq[j]);
    }
    __syncthreads();
    if (tid < 128) {
        atomicAdd(&g_sum[tid], red0[tid]);
        atomicAdd(&g_sq [tid], red1[tid]);
    }
}

// ---------------- scatter: fused msg-BN finalize + 8 cols/thread ----------------
__global__ void __launch_bounds__(256) scatter_kernel(const int* __restrict__ dst,
                                                      const float* __restrict__ bng,
                                                      const float* __restrict__ bnb) {
    __shared__ float ssc[128], ssh[128];
    const int tid = threadIdx.x;
    if (tid < 128) {
        const float invE = 1.f / (float)N_EDGES;
        float mean = g_sum[tid] * invE;
        float var  = fmaxf(g_sq[tid] * invE - mean * mean, 0.f);
        float a = bng[tid] * rsqrtf(var + 1e-5f);
        ssc[tid] = a;
        ssh[tid] = fmaf(-mean, a, bnb[tid]);
    }
    __syncthreads();

    unsigned t = blockIdx.x * blockDim.x + tid;
    size_t e = (size_t)(t >> 4);       // 16 threads per edge
    int c8 = (t & 15) * 8;
    if (e < (size_t)N_EDGES) {
        int d = dst[e];
        uint4 m4 = *(const uint4*)(g_MSGh + e * HDIM + c8);
        float4 m0 = unpack_half4(m4.x, m4.y);
        float4 m1 = unpack_half4(m4.z, m4.w);
        float4 s0 = *(const float4*)&ssc[c8];
        float4 s1 = *(const float4*)&ssc[c8 + 4];
        float4 h0 = *(const float4*)&ssh[c8];
        float4 h1 = *(const float4*)&ssh[c8 + 4];
        float v0 = fmaxf(fmaf(m0.x, s0.x, h0.x), 0.f);
        float v1 = fmaxf(fmaf(m0.y, s0.y, h0.y), 0.f);
        float v2 = fmaxf(fmaf(m0.z, s0.z, h0.z), 0.f);
        float v3 = fmaxf(fmaf(m0.w, s0.w, h0.w), 0.f);
        float v4 = fmaxf(fmaf(m1.x, s1.x, h1.x), 0.f);
        float v5 = fmaxf(fmaf(m1.y, s1.y, h1.y), 0.f);
        float v6 = fmaxf(fmaf(m1.z, s1.z, h1.z), 0.f);
        float v7 = fmaxf(fmaf(m1.w, s1.w, h1.w), 0.f);
        float* p = g_Y + (size_t)d * HDIM + c8;
        asm volatile("red.global.add.v4.f32 [%0], {%1,%2,%3,%4};"
                     :: "l"(p), "f"(v0), "f"(v1), "f"(v2), "f"(v3) : "memory");
        asm volatile("red.global.add.v4.f32 [%0], {%1,%2,%3,%4};"
                     :: "l"(p + 4), "f"(v4), "f"(v5), "f"(v6), "f"(v7) : "memory");
    }
}

// ---------------- launch ------------------------------------------------------
extern "C" void kernel_launch(void* const* d_in, const int* in_sizes, int n_in,
                              void* d_out, int out_size) {
    const float* node_rep  = (const float*)d_in[0];
    const float* edge_rep  = (const float*)d_in[1];
    const float* edge_attr = (const float*)d_in[2];
    const int*   eidx      = (const int*)d_in[3];
    const float* W1  = (const float*)d_in[4];
    const float* W2  = (const float*)d_in[5];
    const float* W3  = (const float*)d_in[6];
    const float* We  = (const float*)d_in[7];
    const float* be  = (const float*)d_in[8];
    const float* bng = (const float*)d_in[9];
    const float* bnb = (const float*)d_in[10];
    const float* Wm1 = (const float*)d_in[11];
    const float* g1  = (const float*)d_in[12];
    const float* b1  = (const float*)d_in[13];
    const float* Wm2 = (const float*)d_in[14];
    const float* g2  = (const float*)d_in[15];
    const float* b2  = (const float*)d_in[16];
    const float* Wm3 = (const float*)d_in[17];
    const float* bm3 = (const float*)d_in[18];
    float* out = (float*)d_out;

    const int* src = eidx;
    const int* dst = eidx + N_EDGES;

    float *Y, *H1, *H2, *SUM, *SQ;
    __half *PQh, *WH;
    cudaGetSymbolAddress((void**)&PQh, g_PQh);
    cudaGetSymbolAddress((void**)&Y,  g_Y);
    cudaGetSymbolAddress((void**)&H1, g_H1);
    cudaGetSymbolAddress((void**)&H2, g_H2);
    cudaGetSymbolAddress((void**)&SUM, g_sum);
    cudaGetSymbolAddress((void**)&SQ,  g_sq);
    cudaGetSymbolAddress((void**)&WH,  g_WallH);

    const int GEMM_SMEM = G_PIPE + 2048 + 1024;   // 95232
    const int EDGE_SMEM = E_PIPE + 1024;          // 41984
    cudaFuncSetAttribute(gemm_mma_kernel, cudaFuncAttributeMaxDynamicSharedMemorySize, GEMM_SMEM);
    cudaFuncSetAttribute(edge_msg_kernel, cudaFuncAttributeMaxDynamicSharedMemorySize, EDGE_SMEM);

    const int MBLK = (N_NODES + 127) / 128;  // 782
    const float invN = 1.f / (float)N_NODES;

    prep_kernel<<<4096, 256>>>(W1, W2, W3, We, Wm1, Wm2, Wm3);

    // fused node linears: PQ = node_rep @ [W1|W2] -> fp16
    gemm_mma_kernel<<<dim3(2, MBLK), 256, GEMM_SMEM>>>(
        node_rep, WH + OFF_NODE, HDIM, PQh, N_NODES, HDIM, 256, 1,
        nullptr, nullptr, nullptr, nullptr, 0.f, nullptr, nullptr, nullptr);

    // edge GEMM (fp16 HMMA, occ-4) + encoder + gathers + BN stats
    edge_msg_kernel<<<N_EDGES / 64, 256, EDGE_SMEM>>>(edge_rep, edge_attr, src, dst, be);

    // BN finalize (in-block) + BN + ReLU + scatter-sum
    scatter_kernel<<<(N_EDGES * 16) / 256, 256>>>(dst, bng, bnb);

    // MLP layer 1: H1 = Y @ Wm1, stats -> slot 128
    gemm_mma_kernel<<<dim3(2, MBLK), 256, GEMM_SMEM>>>(
        Y, WH + OFF_M1, HDIM, H1, N_NODES, HDIM, H2DIM, 0,
        nullptr, nullptr, nullptr, nullptr, 0.f, nullptr, SUM + 128, SQ + 128);

    // MLP layer 2: H2 = relu(bn1(H1)) @ Wm2 (bn1 finalize fused in-kernel)
    gemm_mma_kernel<<<dim3(2, MBLK), 256, GEMM_SMEM>>>(
        H1, WH + OFF_M2, H2DIM, H2, N_NODES, H2DIM, H2DIM, 0,
        g1, b1, SUM + 128, SQ + 128, invN, nullptr, SUM + 384, SQ + 384);

    // MLP layer 3: out = relu(bn2(H2)) @ Wm3 + bm3 (bn2 finalize fused in-kernel)
    gemm_mma_kernel<<<dim3(1, MBLK), 256, GEMM_SMEM>>>(
        H2, WH + OFF_M3, H2DIM, out, N_NODES, H2DIM, HDIM, 0,
        g2, b2, SUM + 384, SQ + 384, invN, bm3, nullptr, nullptr);
}